// round 1
// baseline (speedup 1.0000x reference)
#include <cuda_runtime.h>
#include <math.h>

// Problem dimensions (fixed by the dataset)
#define BQ   1024      // batch of graphs
#define TT   64        // time steps
#define HD   512       // hidden dim
#define H3   1536      // 3*H
#define GC   3072      // gi (1536) + gh (1536) columns in the gates scratch
#define LN_EPS 1e-5f

// GEMM tiling
#define BM 128
#define BN 64
#define BK 16

// Persistent scratch (allowed: __device__ globals, no runtime allocation)
__device__ float g_h[BQ * HD];        // recurrent state  [B,H]
__device__ float g_gates[BQ * GC];    // per-step gates   [B, 3H(gi) | 3H(gh)]
__device__ int   g_done[BQ];          // done flags

// ---------------------------------------------------------------------------
// block-wide sum over 256 threads
// ---------------------------------------------------------------------------
__device__ __forceinline__ float block_sum_256(float v, float* red)
{
    int lane = threadIdx.x & 31;
    int w    = threadIdx.x >> 5;
    #pragma unroll
    for (int o = 16; o > 0; o >>= 1) v += __shfl_xor_sync(0xffffffffu, v, o);
    if (lane == 0) red[w] = v;
    __syncthreads();
    if (w == 0) {
        float x = (lane < 8) ? red[lane] : 0.0f;
        #pragma unroll
        for (int o = 4; o > 0; o >>= 1) x += __shfl_xor_sync(0xffffffffu, x, o);
        if (lane == 0) red[0] = x;
    }
    __syncthreads();
    float r = red[0];
    __syncthreads();   // protect red[] for back-to-back reductions
    return r;
}

// ---------------------------------------------------------------------------
// init: start_state = segment-mean(node_tokens[start_node_locals]) per graph
//       h0 = LN(question + start_state) ; done = 0
// one block (256 thr) per graph row
// ---------------------------------------------------------------------------
__global__ void init_kernel(const float* __restrict__ question,
                            const float* __restrict__ node_tokens,
                            const int*   __restrict__ locals,
                            const int*   __restrict__ ptr,
                            const float* __restrict__ ln_w,
                            const float* __restrict__ ln_b)
{
    __shared__ float red[8];
    int b   = blockIdx.x;
    int tid = threadIdx.x;

    int p0 = ptr[b], p1 = ptr[b + 1];
    int cnt = p1 - p0;
    float inv = 1.0f / (float)(cnt > 0 ? cnt : 1);

    float x0, x1;
    {
        float s0 = 0.0f, s1 = 0.0f;
        for (int j = p0; j < p1; j++) {
            int node = locals[j];
            const float* nrow = node_tokens + (size_t)node * HD;
            s0 += nrow[tid];
            s1 += nrow[tid + 256];
        }
        const float* qrow = question + (size_t)b * HD;
        x0 = qrow[tid]       + s0 * inv;
        x1 = qrow[tid + 256] + s1 * inv;
    }

    float mean = block_sum_256(x0 + x1, red) * (1.0f / (float)HD);
    float d0 = x0 - mean, d1 = x1 - mean;
    float var  = block_sum_256(d0 * d0 + d1 * d1, red) * (1.0f / (float)HD);
    float rstd = rsqrtf(var + LN_EPS);

    float* hrow = g_h + (size_t)b * HD;
    hrow[tid]       = d0 * rstd * ln_w[tid]       + ln_b[tid];
    hrow[tid + 256] = d1 * rstd * ln_w[tid + 256] + ln_b[tid + 256];
    if (tid == 0) g_done[b] = 0;
}

// ---------------------------------------------------------------------------
// Per-step GEMM: g_gates[b, 0:1536)    = edge_tokens[clip(a_t[b])] @ w_ih^T + b_ih
//                g_gates[b, 1536:3072) = h[b] @ w_hh^T + b_hh
// CTA tile 128x64, BK=16, 128 threads, 8x8 microtile.
// grid = (GC/BN = 48, BQ/BM = 8)
// ---------------------------------------------------------------------------
__global__ __launch_bounds__(128)
void gemm_step_kernel(const float* __restrict__ edge_tokens,
                      const int*   __restrict__ actions,
                      const float* __restrict__ w_ih,
                      const float* __restrict__ w_hh,
                      const float* __restrict__ b_ih,
                      const float* __restrict__ b_hh,
                      int t, int E)
{
    __shared__ __align__(16) float As[BK][BM + 4];
    __shared__ __align__(16) float Bs[BK][BN + 4];

    const int tid  = threadIdx.x;
    const int col0 = blockIdx.x * BN;
    const int row0 = blockIdx.y * BM;
    const bool is_gi = (col0 < H3);
    const float* __restrict__ W    = is_gi ? w_ih : w_hh;
    const float* __restrict__ bias = is_gi ? b_ih : b_hh;
    const int wcol0 = is_gi ? col0 : (col0 - H3);

    // loaders: ka = k offset (0/4/8/12), ra = 0..31
    const int ka = (tid & 3) * 4;
    const int ra = tid >> 2;

    const float* aptr[4];
    #pragma unroll
    for (int i = 0; i < 4; i++) {
        int r = row0 + ra + 32 * i;
        if (is_gi) {
            int a = actions[r * TT + t];
            a = a < 0 ? 0 : (a >= E ? E - 1 : a);
            aptr[i] = edge_tokens + (size_t)a * HD;
        } else {
            aptr[i] = g_h + (size_t)r * HD;
        }
    }
    const float* bptr0 = W + (size_t)(wcol0 + ra) * HD;
    const float* bptr1 = W + (size_t)(wcol0 + ra + 32) * HD;

    // microtile: 16x8 thread grid -> each thread 8 rows x 8 cols
    const int tm = (tid >> 3) * 8;
    const int tn = (tid & 7)  * 8;

    float acc[8][8];
    #pragma unroll
    for (int i = 0; i < 8; i++)
        #pragma unroll
        for (int j = 0; j < 8; j++) acc[i][j] = 0.0f;

    float4 a_regs[4], b_regs[2];
    #pragma unroll
    for (int i = 0; i < 4; i++) a_regs[i] = *(const float4*)(aptr[i] + ka);
    b_regs[0] = *(const float4*)(bptr0 + ka);
    b_regs[1] = *(const float4*)(bptr1 + ka);

    #pragma unroll 1
    for (int kt = 0; kt < HD / BK; kt++) {
        // stage to smem (k-major, padded)
        #pragma unroll
        for (int i = 0; i < 4; i++) {
            As[ka + 0][ra + 32 * i] = a_regs[i].x;
            As[ka + 1][ra + 32 * i] = a_regs[i].y;
            As[ka + 2][ra + 32 * i] = a_regs[i].z;
            As[ka + 3][ra + 32 * i] = a_regs[i].w;
        }
        Bs[ka + 0][ra]      = b_regs[0].x;
        Bs[ka + 1][ra]      = b_regs[0].y;
        Bs[ka + 2][ra]      = b_regs[0].z;
        Bs[ka + 3][ra]      = b_regs[0].w;
        Bs[ka + 0][ra + 32] = b_regs[1].x;
        Bs[ka + 1][ra + 32] = b_regs[1].y;
        Bs[ka + 2][ra + 32] = b_regs[1].z;
        Bs[ka + 3][ra + 32] = b_regs[1].w;
        __syncthreads();

        // prefetch next k-tile while computing
        if (kt + 1 < HD / BK) {
            int kn = (kt + 1) * BK + ka;
            #pragma unroll
            for (int i = 0; i < 4; i++) a_regs[i] = *(const float4*)(aptr[i] + kn);
            b_regs[0] = *(const float4*)(bptr0 + kn);
            b_regs[1] = *(const float4*)(bptr1 + kn);
        }

        #pragma unroll
        for (int k = 0; k < BK; k++) {
            float4 a0 = *(const float4*)&As[k][tm];
            float4 a1 = *(const float4*)&As[k][tm + 4];
            float4 b0 = *(const float4*)&Bs[k][tn];
            float4 b1 = *(const float4*)&Bs[k][tn + 4];
            float av[8] = {a0.x, a0.y, a0.z, a0.w, a1.x, a1.y, a1.z, a1.w};
            float bv[8] = {b0.x, b0.y, b0.z, b0.w, b1.x, b1.y, b1.z, b1.w};
            #pragma unroll
            for (int i = 0; i < 8; i++)
                #pragma unroll
                for (int j = 0; j < 8; j++)
                    acc[i][j] = fmaf(av[i], bv[j], acc[i][j]);
        }
        __syncthreads();
    }

    // epilogue: + bias, vectorized store
    float bv[8];
    #pragma unroll
    for (int j = 0; j < 8; j++) bv[j] = bias[wcol0 + tn + j];
    #pragma unroll
    for (int i = 0; i < 8; i++) {
        float4 o0, o1;
        o0.x = acc[i][0] + bv[0]; o0.y = acc[i][1] + bv[1];
        o0.z = acc[i][2] + bv[2]; o0.w = acc[i][3] + bv[3];
        o1.x = acc[i][4] + bv[4]; o1.y = acc[i][5] + bv[5];
        o1.z = acc[i][6] + bv[6]; o1.w = acc[i][7] + bv[7];
        float* dst = g_gates + (size_t)(row0 + tm + i) * GC + col0 + tn;
        *(float4*)(dst)     = o0;
        *(float4*)(dst + 4) = o1;
    }
}

// ---------------------------------------------------------------------------
// Per-step elementwise: emit emb_t = LN(h) (pre-update), then GRU update
// masked by active = !done && !is_stop. One block (256 thr) per graph row.
// ---------------------------------------------------------------------------
__global__ void update_kernel(const int*   __restrict__ actions,
                              const int*   __restrict__ stop_idx,
                              const float* __restrict__ ln_w,
                              const float* __restrict__ ln_b,
                              float* __restrict__ out, int t)
{
    __shared__ float red[8];
    int b   = blockIdx.x;
    int tid = threadIdx.x;

    float* hrow = g_h + (size_t)b * HD;
    float h0 = hrow[tid];
    float h1 = hrow[tid + 256];

    float mean = block_sum_256(h0 + h1, red) * (1.0f / (float)HD);
    float d0 = h0 - mean, d1 = h1 - mean;
    float var  = block_sum_256(d0 * d0 + d1 * d1, red) * (1.0f / (float)HD);
    float rstd = rsqrtf(var + LN_EPS);

    float* orow = out + ((size_t)b * TT + t) * HD;
    orow[tid]       = d0 * rstd * ln_w[tid]       + ln_b[tid];
    orow[tid + 256] = d1 * rstd * ln_w[tid + 256] + ln_b[tid + 256];

    int a = actions[b * TT + t];
    bool is_stop = (a == stop_idx[b]) || (a < 0);
    bool done    = (g_done[b] != 0);
    bool active  = (!done) && (!is_stop);

    if (active) {
        const float* G = g_gates + (size_t)b * GC;
        #pragma unroll
        for (int e = 0; e < 2; e++) {
            int i = tid + e * 256;
            float ir  = G[i];
            float iz  = G[i + 512];
            float inn = G[i + 1024];
            float hr  = G[i + 1536];
            float hz  = G[i + 2048];
            float hn  = G[i + 2560];
            float r = 1.0f / (1.0f + expf(-(ir + hr)));
            float z = 1.0f / (1.0f + expf(-(iz + hz)));
            float n = tanhf(inn + r * hn);
            float hcur = (e == 0) ? h0 : h1;
            hrow[i] = (1.0f - z) * n + z * hcur;
        }
    }
    if (tid == 0 && is_stop) g_done[b] = 1;
}

// ---------------------------------------------------------------------------
// Launch: init, then 64 x (gemm, update). All stream-ordered; graph-capturable.
// ---------------------------------------------------------------------------
extern "C" void kernel_launch(void* const* d_in, const int* in_sizes, int n_in,
                              void* d_out, int out_size)
{
    const int*   actions      = (const int*)  d_in[0];
    const float* edge_tokens  = (const float*)d_in[1];
    const int*   stop_indices = (const int*)  d_in[2];
    const float* question     = (const float*)d_in[3];
    const float* node_tokens  = (const float*)d_in[4];
    const int*   start_locals = (const int*)  d_in[5];
    const int*   start_ptr    = (const int*)  d_in[6];
    const float* w_ih         = (const float*)d_in[7];
    const float* w_hh         = (const float*)d_in[8];
    const float* b_ih         = (const float*)d_in[9];
    const float* b_hh         = (const float*)d_in[10];
    const float* ln_w         = (const float*)d_in[11];
    const float* ln_b         = (const float*)d_in[12];
    float* out = (float*)d_out;

    const int E = in_sizes[1] / HD;   // number of edge tokens

    init_kernel<<<BQ, 256>>>(question, node_tokens, start_locals, start_ptr,
                             ln_w, ln_b);

    dim3 ggrid(GC / BN, BQ / BM);   // (48, 8) = 384 CTAs
    for (int t = 0; t < TT; t++) {
        gemm_step_kernel<<<ggrid, 128>>>(edge_tokens, actions, w_ih, w_hh,
                                         b_ih, b_hh, t, E);
        update_kernel<<<BQ, 256>>>(actions, stop_indices, ln_w, ln_b, out, t);
    }
}

// round 3
// speedup vs baseline: 1.6165x; 1.6165x over previous
#include <cuda_runtime.h>
#include <cuda_bf16.h>
#include <math.h>
#include <stdint.h>

// ---------------- problem dims ----------------
#define BQ   1024
#define TT   64
#define HD   512
#define H3   1536
#define MGI  (BQ * TT)          // 65536 rows of the batched gi GEMM
#define KTOT 1536               // K' = 3 * 512 (bf16x3 split folded into K)
#define LN_EPS 1e-5f

// ---------------- GEMM tiling ----------------
#define BM 128
#define BN 128
#define BK 32
#define KITERS (KTOT / BK)      // 48
#define SA 40                   // padded smem row stride (bf16 elems)

// ---------------- device scratch ----------------
__device__ __nv_bfloat16 g_Agi[(size_t)MGI * KTOT];   // expanded gathered edge rows
__device__ float         g_gi [(size_t)MGI * H3];     // gi output (fp32)
__device__ __nv_bfloat16 g_W2ih[(size_t)H3 * KTOT];   // [Wh | Wh | Wl]
__device__ __nv_bfloat16 g_W2hh[(size_t)H3 * KTOT];
__device__ __nv_bfloat16 g_h2[(size_t)BQ * KTOT];     // [hh | hl | hh]
__device__ float         g_h  [(size_t)BQ * HD];
__device__ float         g_gh [(size_t)BQ * H3];      // gh output per step
__device__ int           g_done[BQ];

// ---------------- helpers ----------------
__device__ __forceinline__ uint32_t smem_u32(const void* p) {
    uint32_t a;
    asm("{ .reg .u64 t; cvta.to.shared.u64 t, %1; cvt.u32.u64 %0, t; }" : "=r"(a) : "l"(p));
    return a;
}

#define CP_ASYNC16(dst, src) \
    asm volatile("cp.async.cg.shared.global [%0], [%1], 16;" :: "r"(dst), "l"(src))
#define CP_COMMIT() asm volatile("cp.async.commit_group;" ::: "memory")
#define CP_WAIT0()  asm volatile("cp.async.wait_group 0;" ::: "memory")
#define CP_WAIT1()  asm volatile("cp.async.wait_group 1;" ::: "memory")

__device__ __forceinline__ void mma16816(float* c, const uint32_t* a,
                                         uint32_t b0, uint32_t b1)
{
    asm volatile(
        "mma.sync.aligned.m16n8k16.row.col.f32.bf16.bf16.f32 "
        "{%0,%1,%2,%3}, {%4,%5,%6,%7}, {%8,%9}, {%0,%1,%2,%3};"
        : "+f"(c[0]), "+f"(c[1]), "+f"(c[2]), "+f"(c[3])
        : "r"(a[0]), "r"(a[1]), "r"(a[2]), "r"(a[3]), "r"(b0), "r"(b1));
}

// ---------------------------------------------------------------------------
// bf16 GEMM: out[M, H3] (fp32, stride H3) = A[M, KTOT] x B[H3, KTOT]^T
// CTA 128x128, BK=32, 256 threads (8 warps, warp tile 64x32), cp.async 2-stage.
// grid = (H3/BN = 12, M/BM)
// ---------------------------------------------------------------------------
__global__ __launch_bounds__(256)
void gemm_mma(const __nv_bfloat16* __restrict__ A,
              const __nv_bfloat16* __restrict__ B,
              float* __restrict__ out)
{
    __shared__ __align__(16) __nv_bfloat16 smA[2][BM * SA];
    __shared__ __align__(16) __nv_bfloat16 smB[2][BN * SA];

    const int tid  = threadIdx.x;
    const int lane = tid & 31;
    const int w    = tid >> 5;
    const int wr   = w & 1;        // 2 m-warps
    const int wc   = w >> 1;       // 4 n-warps
    const int qr   = lane >> 2;    // 0..7
    const int qc   = lane & 3;     // 0..3

    const int col0 = blockIdx.x * BN;
    const int row0 = blockIdx.y * BM;

    // loader mapping: chunks of 16B (8 bf16); 4 chunks per row
    const int lrow = tid >> 2;          // 0..63
    const int lseg = (tid & 3) * 8;     // 0,8,16,24 (bf16 elems)

    const __nv_bfloat16* gA0 = A + (size_t)(row0 + lrow) * KTOT + lseg;
    const __nv_bfloat16* gA1 = A + (size_t)(row0 + lrow + 64) * KTOT + lseg;
    const __nv_bfloat16* gB0 = B + (size_t)(col0 + lrow) * KTOT + lseg;
    const __nv_bfloat16* gB1 = B + (size_t)(col0 + lrow + 64) * KTOT + lseg;

    const uint32_t sA0[2] = { smem_u32(&smA[0][lrow * SA + lseg]),
                              smem_u32(&smA[1][lrow * SA + lseg]) };
    const uint32_t sA1[2] = { smem_u32(&smA[0][(lrow + 64) * SA + lseg]),
                              smem_u32(&smA[1][(lrow + 64) * SA + lseg]) };
    const uint32_t sB0[2] = { smem_u32(&smB[0][lrow * SA + lseg]),
                              smem_u32(&smB[1][lrow * SA + lseg]) };
    const uint32_t sB1[2] = { smem_u32(&smB[0][(lrow + 64) * SA + lseg]),
                              smem_u32(&smB[1][(lrow + 64) * SA + lseg]) };

    float acc[4][4][4];
    #pragma unroll
    for (int i = 0; i < 4; i++)
        #pragma unroll
        for (int j = 0; j < 4; j++)
            #pragma unroll
            for (int v = 0; v < 4; v++) acc[i][j][v] = 0.0f;

    // prologue: stage 0
    {
        CP_ASYNC16(sA0[0], gA0);
        CP_ASYNC16(sA1[0], gA1);
        CP_ASYNC16(sB0[0], gB0);
        CP_ASYNC16(sB1[0], gB1);
        CP_COMMIT();
    }

    #pragma unroll 1
    for (int kt = 0; kt < KITERS; kt++) {
        int buf = kt & 1;
        if (kt + 1 < KITERS) {
            int nb = (kt + 1) & 1;
            size_t off = (size_t)(kt + 1) * BK;
            CP_ASYNC16(sA0[nb], gA0 + off);
            CP_ASYNC16(sA1[nb], gA1 + off);
            CP_ASYNC16(sB0[nb], gB0 + off);
            CP_ASYNC16(sB1[nb], gB1 + off);
            CP_COMMIT();
            CP_WAIT1();
        } else {
            CP_WAIT0();
        }
        __syncthreads();

        const __nv_bfloat16* As = smA[buf];
        const __nv_bfloat16* Bs = smB[buf];

        #pragma unroll
        for (int ks = 0; ks < 2; ks++) {
            const int kb = ks * 16 + qc * 2;
            uint32_t afr[4][4];
            #pragma unroll
            for (int mi = 0; mi < 4; mi++) {
                int r = wr * 64 + mi * 16 + qr;
                afr[mi][0] = *(const uint32_t*)&As[r * SA + kb];
                afr[mi][1] = *(const uint32_t*)&As[(r + 8) * SA + kb];
                afr[mi][2] = *(const uint32_t*)&As[r * SA + kb + 8];
                afr[mi][3] = *(const uint32_t*)&As[(r + 8) * SA + kb + 8];
            }
            #pragma unroll
            for (int ni = 0; ni < 4; ni++) {
                int n = wc * 32 + ni * 8 + qr;
                uint32_t b0 = *(const uint32_t*)&Bs[n * SA + kb];
                uint32_t b1 = *(const uint32_t*)&Bs[n * SA + kb + 8];
                #pragma unroll
                for (int mi = 0; mi < 4; mi++)
                    mma16816(acc[mi][ni], afr[mi], b0, b1);
            }
        }
        __syncthreads();
    }

    // epilogue: direct float2 stores
    #pragma unroll
    for (int mi = 0; mi < 4; mi++) {
        int r = row0 + wr * 64 + mi * 16 + qr;
        #pragma unroll
        for (int ni = 0; ni < 4; ni++) {
            int c = col0 + wc * 32 + ni * 8 + qc * 2;
            float2 v0 = make_float2(acc[mi][ni][0], acc[mi][ni][1]);
            float2 v1 = make_float2(acc[mi][ni][2], acc[mi][ni][3]);
            *(float2*)(out + (size_t)r * H3 + c)       = v0;
            *(float2*)(out + (size_t)(r + 8) * H3 + c) = v1;
        }
    }
}

// ---------------------------------------------------------------------------
// prep: weights -> [Wh | Wh | Wl] bf16
// ---------------------------------------------------------------------------
__global__ void prep_weights(const float* __restrict__ wih,
                             const float* __restrict__ whh)
{
    int n = blockIdx.x;
    const float* src = (blockIdx.y == 0 ? wih : whh) + (size_t)n * HD;
    __nv_bfloat16* dst = (blockIdx.y == 0 ? g_W2ih : g_W2hh) + (size_t)n * KTOT;
    for (int k = threadIdx.x; k < HD; k += 128) {
        float x = src[k];
        __nv_bfloat16 hi = __float2bfloat16(x);
        float lo = x - __bfloat162float(hi);
        dst[k] = hi; dst[HD + k] = hi; dst[2 * HD + k] = __float2bfloat16(lo);
    }
}

// ---------------------------------------------------------------------------
// prep: gathered edge rows -> [Ah | Al | Ah] bf16, row m = t*B + b
// ---------------------------------------------------------------------------
__global__ void prep_agi(const int* __restrict__ actions,
                         const float* __restrict__ edge_tokens, int E)
{
    int m = blockIdx.x;
    int t = m >> 10, b = m & (BQ - 1);
    int a = actions[b * TT + t];
    a = a < 0 ? 0 : (a >= E ? E - 1 : a);
    const float* src = edge_tokens + (size_t)a * HD;
    __nv_bfloat16* dst = g_Agi + (size_t)m * KTOT;
    for (int k = threadIdx.x; k < HD; k += 128) {
        float x = src[k];
        __nv_bfloat16 hi = __float2bfloat16(x);
        float lo = x - __bfloat162float(hi);
        dst[k] = hi; dst[HD + k] = __float2bfloat16(lo); dst[2 * HD + k] = hi;
    }
}

// ---------------------------------------------------------------------------
// reductions + init + update
// ---------------------------------------------------------------------------
__device__ __forceinline__ float block_sum_256(float v, float* red)
{
    int lane = threadIdx.x & 31, w = threadIdx.x >> 5;
    #pragma unroll
    for (int o = 16; o > 0; o >>= 1) v += __shfl_xor_sync(0xffffffffu, v, o);
    if (lane == 0) red[w] = v;
    __syncthreads();
    if (w == 0) {
        float x = (lane < 8) ? red[lane] : 0.0f;
        #pragma unroll
        for (int o = 4; o > 0; o >>= 1) x += __shfl_xor_sync(0xffffffffu, x, o);
        if (lane == 0) red[0] = x;
    }
    __syncthreads();
    float r = red[0];
    __syncthreads();
    return r;
}

__device__ __forceinline__ void write_h2(__nv_bfloat16* h2row, int i, float v)
{
    __nv_bfloat16 hi = __float2bfloat16(v);
    h2row[i] = hi;
    h2row[HD + i] = __float2bfloat16(v - __bfloat162float(hi));
    h2row[2 * HD + i] = hi;
}

__global__ void init_kernel(const float* __restrict__ question,
                            const float* __restrict__ node_tokens,
                            const int*   __restrict__ locals,
                            const int*   __restrict__ ptr,
                            const float* __restrict__ ln_w,
                            const float* __restrict__ ln_b)
{
    __shared__ float red[8];
    int b = blockIdx.x, tid = threadIdx.x;
    int p0 = ptr[b], p1 = ptr[b + 1];
    int cnt = p1 - p0;
    float inv = 1.0f / (float)(cnt > 0 ? cnt : 1);

    float s0 = 0.0f, s1 = 0.0f;
    for (int j = p0; j < p1; j++) {
        const float* nrow = node_tokens + (size_t)locals[j] * HD;
        s0 += nrow[tid]; s1 += nrow[tid + 256];
    }
    const float* q = question + (size_t)b * HD;
    float x0 = q[tid] + s0 * inv, x1 = q[tid + 256] + s1 * inv;

    float mean = block_sum_256(x0 + x1, red) * (1.0f / HD);
    float d0 = x0 - mean, d1 = x1 - mean;
    float var = block_sum_256(d0 * d0 + d1 * d1, red) * (1.0f / HD);
    float rstd = rsqrtf(var + LN_EPS);

    float v0 = d0 * rstd * ln_w[tid] + ln_b[tid];
    float v1 = d1 * rstd * ln_w[tid + 256] + ln_b[tid + 256];
    float* hrow = g_h + (size_t)b * HD;
    hrow[tid] = v0; hrow[tid + 256] = v1;
    __nv_bfloat16* h2row = g_h2 + (size_t)b * KTOT;
    write_h2(h2row, tid, v0);
    write_h2(h2row, tid + 256, v1);
    if (tid == 0) g_done[b] = 0;
}

__global__ void update_kernel(const int*   __restrict__ actions,
                              const int*   __restrict__ stop_idx,
                              const float* __restrict__ b_ih,
                              const float* __restrict__ b_hh,
                              const float* __restrict__ ln_w,
                              const float* __restrict__ ln_b,
                              float* __restrict__ out, int t)
{
    __shared__ float red[8];
    int b = blockIdx.x, tid = threadIdx.x;

    float* hrow = g_h + (size_t)b * HD;
    float h0 = hrow[tid], h1 = hrow[tid + 256];

    float mean = block_sum_256(h0 + h1, red) * (1.0f / HD);
    float d0 = h0 - mean, d1 = h1 - mean;
    float var = block_sum_256(d0 * d0 + d1 * d1, red) * (1.0f / HD);
    float rstd = rsqrtf(var + LN_EPS);

    float* orow = out + ((size_t)b * TT + t) * HD;
    orow[tid]       = d0 * rstd * ln_w[tid] + ln_b[tid];
    orow[tid + 256] = d1 * rstd * ln_w[tid + 256] + ln_b[tid + 256];

    int a = actions[b * TT + t];
    bool is_stop = (a == stop_idx[b]) || (a < 0);
    bool active = (g_done[b] == 0) && (!is_stop);

    if (active) {
        const float* GI = g_gi + (size_t)((size_t)t * BQ + b) * H3;
        const float* GH = g_gh + (size_t)b * H3;
        __nv_bfloat16* h2row = g_h2 + (size_t)b * KTOT;
        #pragma unroll
        for (int e = 0; e < 2; e++) {
            int i = tid + e * 256;
            float ir = GI[i]        + b_ih[i];
            float iz = GI[i + 512]  + b_ih[i + 512];
            float in = GI[i + 1024] + b_ih[i + 1024];
            float hr = GH[i]        + b_hh[i];
            float hz = GH[i + 512]  + b_hh[i + 512];
            float hn = GH[i + 1024] + b_hh[i + 1024];
            float r = 1.0f / (1.0f + expf(-(ir + hr)));
            float z = 1.0f / (1.0f + expf(-(iz + hz)));
            float n = tanhf(in + r * hn);
            float hcur = (e == 0) ? h0 : h1;
            float hnew = (1.0f - z) * n + z * hcur;
            hrow[i] = hnew;
            write_h2(h2row, i, hnew);
        }
    }
    if (tid == 0 && is_stop) g_done[b] = 1;
}

// ---------------------------------------------------------------------------
// launch
// ---------------------------------------------------------------------------
extern "C" void kernel_launch(void* const* d_in, const int* in_sizes, int n_in,
                              void* d_out, int out_size)
{
    const int*   actions      = (const int*)  d_in[0];
    const float* edge_tokens  = (const float*)d_in[1];
    const int*   stop_indices = (const int*)  d_in[2];
    const float* question     = (const float*)d_in[3];
    const float* node_tokens  = (const float*)d_in[4];
    const int*   start_locals = (const int*)  d_in[5];
    const int*   start_ptr    = (const int*)  d_in[6];
    const float* w_ih         = (const float*)d_in[7];
    const float* w_hh         = (const float*)d_in[8];
    const float* b_ih         = (const float*)d_in[9];
    const float* b_hh         = (const float*)d_in[10];
    const float* ln_w         = (const float*)d_in[11];
    const float* ln_b         = (const float*)d_in[12];
    float* out = (float*)d_out;
    const int E = in_sizes[1] / HD;

    void *pAgi, *pWih, *pWhh, *pH2, *pGi, *pGh;
    cudaGetSymbolAddress(&pAgi, g_Agi);
    cudaGetSymbolAddress(&pWih, g_W2ih);
    cudaGetSymbolAddress(&pWhh, g_W2hh);
    cudaGetSymbolAddress(&pH2,  g_h2);
    cudaGetSymbolAddress(&pGi,  g_gi);
    cudaGetSymbolAddress(&pGh,  g_gh);

    // prep
    prep_weights<<<dim3(H3, 2), 128>>>(w_ih, w_hh);
    prep_agi<<<MGI, 128>>>(actions, edge_tokens, E);
    init_kernel<<<BQ, 256>>>(question, node_tokens, start_locals, start_ptr, ln_w, ln_b);

    // batched gi GEMM: [65536, 1536] = Agi x W2ih^T
    gemm_mma<<<dim3(H3 / BN, MGI / BM), 256>>>((const __nv_bfloat16*)pAgi,
                                               (const __nv_bfloat16*)pWih,
                                               (float*)pGi);

    // sequential loop: gh GEMM + fused LN/GRU update
    for (int t = 0; t < TT; t++) {
        gemm_mma<<<dim3(H3 / BN, BQ / BM), 256>>>((const __nv_bfloat16*)pH2,
                                                  (const __nv_bfloat16*)pWhh,
                                                  (float*)pGh);
        update_kernel<<<BQ, 256>>>(actions, stop_indices, b_ih, b_hh, ln_w, ln_b, out, t);
    }
}